// round 1
// baseline (speedup 1.0000x reference)
#include <cuda_runtime.h>
#include <cuda_bf16.h>
#include <math.h>

#define N_NODES 100000
#define E_EDGES 1600000
#define IN_F 20
#define H_F 64
#define NHEADS 4
#define HO_F 32
#define EPS_BN 1e-5f

// ---------------- scratch (device globals; no allocation) ----------------
__device__ float d_deg[N_NODES];
__device__ float d_aggrx[N_NODES * IN_F];
__device__ float d_h1[N_NODES * H_F];
__device__ float d_hg[N_NODES * NHEADS * H_F];     // 102.4 MB
__device__ float d_asrc[N_NODES * NHEADS];
__device__ float d_adst[N_NODES * NHEADS];
__device__ float d_mmax[N_NODES * NHEADS];
__device__ float d_denom[N_NODES * NHEADS];
__device__ float d_ex[E_EDGES * NHEADS];           // 25.6 MB
__device__ float d_gatout[N_NODES * H_F];          // head-mean accumulator (x4 scaled)
__device__ float d_h2[N_NODES * H_F];
__device__ float d_aggr2[N_NODES * H_F];
__device__ float d_h3[N_NODES * HO_F];

// ---------------- helpers ----------------
__device__ __forceinline__ void red_add_v4(float* addr, float4 v) {
    asm volatile("red.global.add.v4.f32 [%0], {%1,%2,%3,%4};"
                 :: "l"(addr), "f"(v.x), "f"(v.y), "f"(v.z), "f"(v.w) : "memory");
}
__device__ __forceinline__ void red_add_v2(float* addr, float2 v) {
    asm volatile("red.global.add.v2.f32 [%0], {%1,%2};"
                 :: "l"(addr), "f"(v.x), "f"(v.y) : "memory");
}
__device__ __forceinline__ void atomicMaxFloat(float* addr, float v) {
    if (v >= 0.0f) atomicMax((int*)addr, __float_as_int(v));
    else           atomicMin((unsigned int*)addr, __float_as_uint(v));
}

// ---------------- 0: init scratch ----------------
__global__ void k_init() {
    int i = blockIdx.x * blockDim.x + threadIdx.x;
    if (i < N_NODES) d_deg[i] = 0.0f;
    if (i < N_NODES * IN_F) d_aggrx[i] = 0.0f;
    if (i < N_NODES * NHEADS) { d_mmax[i] = -3.402823466e38f; d_denom[i] = 0.0f; }
    if (i < N_NODES * H_F) { d_gatout[i] = 0.0f; d_aggr2[i] = 0.0f; }
}

// ---------------- 1: SAGE1 mean aggregation (edge) ----------------
__global__ void k_sage1_aggr(const float* __restrict__ x, const int* __restrict__ ei) {
    int e = blockIdx.x * blockDim.x + threadIdx.x;
    if (e >= E_EDGES) return;
    int s = ei[e];
    int d = ei[E_EDGES + e];
    atomicAdd(&d_deg[d], 1.0f);
    const float4* xs = (const float4*)(x + (size_t)s * IN_F);
    float* out = d_aggrx + (size_t)d * IN_F;
#pragma unroll
    for (int i = 0; i < IN_F / 4; i++) {
        float4 v = __ldg(&xs[i]);
        red_add_v4(out + i * 4, v);
    }
}

// ---------------- 2: SAGE1 GEMM + BN + ReLU ----------------
__global__ void k_sage1_gemm(const float* __restrict__ x,
                             const float* __restrict__ Wl, const float* __restrict__ Wr,
                             const float* __restrict__ b,
                             const float* __restrict__ g, const float* __restrict__ be,
                             const float* __restrict__ m, const float* __restrict__ v) {
    __shared__ float sWl[IN_F * H_F], sWr[IN_F * H_F];
    for (int i = threadIdx.x; i < IN_F * H_F; i += blockDim.x) { sWl[i] = Wl[i]; sWr[i] = Wr[i]; }
    __syncthreads();
    int t = blockIdx.x * blockDim.x + threadIdx.x;
    if (t >= N_NODES * H_F) return;
    int n = t >> 6, j = t & 63;
    float inv = 1.0f / fmaxf(d_deg[n], 1.0f);
    const float* ax = d_aggrx + (size_t)n * IN_F;
    const float* xr = x + (size_t)n * IN_F;
    float acc = b[j];
#pragma unroll
    for (int k = 0; k < IN_F; k++) {
        acc = fmaf(ax[k] * inv, sWl[k * H_F + j], acc);
        acc = fmaf(xr[k], sWr[k * H_F + j], acc);
    }
    float sc = g[j] * rsqrtf(v[j] + EPS_BN);
    float y = (acc - m[j]) * sc + be[j];
    d_h1[t] = fmaxf(y, 0.0f);
}

// ---------------- 3: GAT feature GEMM (h1 @ Wg -> [N,256]) ----------------
__global__ void k_gat_gemm(const float* __restrict__ Wg) {
    __shared__ float sh[4][H_F];
    int local = threadIdx.x >> 6;          // node within block (0..3)
    int j = threadIdx.x & 63;              // output quad index (0..63 -> cols 4j..4j+3)
    int n = blockIdx.x * 4 + local;
    sh[local][j] = d_h1[(size_t)n * H_F + j];
    __syncthreads();
    const float4* W4 = (const float4*)Wg;  // row k: W4[k*64 + j]
    float4 acc = make_float4(0.f, 0.f, 0.f, 0.f);
#pragma unroll
    for (int k = 0; k < H_F; k++) {
        float hv = sh[local][k];
        float4 w = __ldg(&W4[k * 64 + j]);
        acc.x = fmaf(hv, w.x, acc.x);
        acc.y = fmaf(hv, w.y, acc.y);
        acc.z = fmaf(hv, w.z, acc.z);
        acc.w = fmaf(hv, w.w, acc.w);
    }
    ((float4*)d_hg)[(size_t)n * 64 + j] = acc;
}

// ---------------- 4: attention logits per (node, head) ----------------
__global__ void k_gat_att(const float* __restrict__ att_src, const float* __restrict__ att_dst) {
    int n = blockIdx.x;
    int h = threadIdx.x >> 5, lane = threadIdx.x & 31;
    const float* hg = d_hg + (size_t)n * 256 + h * 64;
    float w1a = __ldg(&att_src[h * 64 + lane]), w1b = __ldg(&att_src[h * 64 + 32 + lane]);
    float w2a = __ldg(&att_dst[h * 64 + lane]), w2b = __ldg(&att_dst[h * 64 + 32 + lane]);
    float v0 = hg[lane], v1 = hg[lane + 32];
    float s1 = v0 * w1a + v1 * w1b;
    float s2 = v0 * w2a + v1 * w2b;
#pragma unroll
    for (int o = 16; o; o >>= 1) {
        s1 += __shfl_down_sync(0xffffffffu, s1, o);
        s2 += __shfl_down_sync(0xffffffffu, s2, o);
    }
    if (lane == 0) { d_asrc[n * NHEADS + h] = s1; d_adst[n * NHEADS + h] = s2; }
}

// ---------------- 5: edge segment-max ----------------
__global__ void k_edge_max(const int* __restrict__ ei) {
    int e = blockIdx.x * blockDim.x + threadIdx.x;
    if (e >= E_EDGES) return;
    int s = ei[e], d = ei[E_EDGES + e];
    float4 as = *(const float4*)&d_asrc[s * 4];
    float4 ad = *(const float4*)&d_adst[d * 4];
    float a;
    a = as.x + ad.x; a = a > 0.f ? a : 0.2f * a; atomicMaxFloat(&d_mmax[d * 4 + 0], a);
    a = as.y + ad.y; a = a > 0.f ? a : 0.2f * a; atomicMaxFloat(&d_mmax[d * 4 + 1], a);
    a = as.z + ad.z; a = a > 0.f ? a : 0.2f * a; atomicMaxFloat(&d_mmax[d * 4 + 2], a);
    a = as.w + ad.w; a = a > 0.f ? a : 0.2f * a; atomicMaxFloat(&d_mmax[d * 4 + 3], a);
}

// ---------------- 6: edge exp + denom ----------------
__global__ void k_edge_exp(const int* __restrict__ ei) {
    int e = blockIdx.x * blockDim.x + threadIdx.x;
    if (e >= E_EDGES) return;
    int s = ei[e], d = ei[E_EDGES + e];
    float4 as = *(const float4*)&d_asrc[s * 4];
    float4 ad = *(const float4*)&d_adst[d * 4];
    float4 mm = *(const float4*)&d_mmax[d * 4];
    float a; float4 ex;
    a = as.x + ad.x; a = a > 0.f ? a : 0.2f * a; ex.x = __expf(a - mm.x);
    a = as.y + ad.y; a = a > 0.f ? a : 0.2f * a; ex.y = __expf(a - mm.y);
    a = as.z + ad.z; a = a > 0.f ? a : 0.2f * a; ex.z = __expf(a - mm.z);
    a = as.w + ad.w; a = a > 0.f ? a : 0.2f * a; ex.w = __expf(a - mm.w);
    *(float4*)&d_ex[(size_t)e * 4] = ex;
    red_add_v4(&d_denom[d * 4], ex);
}

// ---------------- 7: edge alpha-weighted aggregation (warp per edge) --------
// accumulates sum over heads of alpha_h * feat_h[d] into d_gatout[dst*64+d]
__global__ void k_edge_aggr(const int* __restrict__ ei) {
    int gt = blockIdx.x * blockDim.x + threadIdx.x;
    int e = gt >> 5;
    int lane = threadIdx.x & 31;
    if (e >= E_EDGES) return;
    int s = ei[e], d = ei[E_EDGES + e];
    float alpha = 0.0f;
    if (lane < 4) alpha = d_ex[(size_t)e * 4 + lane] / (d_denom[d * 4 + lane] + 1e-16f);
    float a0 = __shfl_sync(0xffffffffu, alpha, 0);
    float a1 = __shfl_sync(0xffffffffu, alpha, 1);
    float a2 = __shfl_sync(0xffffffffu, alpha, 2);
    float a3 = __shfl_sync(0xffffffffu, alpha, 3);
    const float2* hgp = (const float2*)(d_hg + (size_t)s * 256);
    float2 v0 = __ldg(&hgp[lane]);
    float2 v1 = __ldg(&hgp[32 + lane]);
    float2 v2 = __ldg(&hgp[64 + lane]);
    float2 v3 = __ldg(&hgp[96 + lane]);
    float2 o;
    o.x = a0 * v0.x + a1 * v1.x + a2 * v2.x + a3 * v3.x;
    o.y = a0 * v0.y + a1 * v1.y + a2 * v2.y + a3 * v3.y;
    red_add_v2(d_gatout + (size_t)d * 64 + lane * 2, o);
}

// ---------------- 8: GAT epilogue: mean over heads + bias + BN + ReLU --------
__global__ void k_gat_epi(const float* __restrict__ bg,
                          const float* __restrict__ g, const float* __restrict__ be,
                          const float* __restrict__ m, const float* __restrict__ v) {
    int t = blockIdx.x * blockDim.x + threadIdx.x;
    if (t >= N_NODES * H_F) return;
    int j = t & 63;
    float y = d_gatout[t] * 0.25f + bg[j];
    float sc = g[j] * rsqrtf(v[j] + EPS_BN);
    y = (y - m[j]) * sc + be[j];
    d_h2[t] = fmaxf(y, 0.0f);
}

// ---------------- 9: SAGE3 aggregation (warp per edge) ----------------
__global__ void k_sage3_aggr(const int* __restrict__ ei) {
    int gt = blockIdx.x * blockDim.x + threadIdx.x;
    int e = gt >> 5;
    int lane = threadIdx.x & 31;
    if (e >= E_EDGES) return;
    int s = ei[e], d = ei[E_EDGES + e];
    float2 v = __ldg(&((const float2*)(d_h2 + (size_t)s * H_F))[lane]);
    red_add_v2(d_aggr2 + (size_t)d * H_F + lane * 2, v);
}

// ---------------- 10: SAGE3 GEMM + BN + ReLU + skip ----------------
__global__ void k_sage3_gemm(const float* __restrict__ x,
                             const float* __restrict__ Wl, const float* __restrict__ Wr,
                             const float* __restrict__ b,
                             const float* __restrict__ g, const float* __restrict__ be,
                             const float* __restrict__ m, const float* __restrict__ v,
                             const float* __restrict__ Wskip, const float* __restrict__ bskip) {
    __shared__ float sWl[H_F * HO_F], sWr[H_F * HO_F], sWs[IN_F * HO_F];
    for (int i = threadIdx.x; i < H_F * HO_F; i += blockDim.x) { sWl[i] = Wl[i]; sWr[i] = Wr[i]; }
    for (int i = threadIdx.x; i < IN_F * HO_F; i += blockDim.x) sWs[i] = Wskip[i];
    __syncthreads();
    int t = blockIdx.x * blockDim.x + threadIdx.x;
    if (t >= N_NODES * HO_F) return;
    int n = t >> 5, j = t & 31;
    float inv = 1.0f / fmaxf(d_deg[n], 1.0f);
    const float* ag = d_aggr2 + (size_t)n * H_F;
    const float* hr = d_h2 + (size_t)n * H_F;
    float accl = 0.0f, accr = 0.0f;
#pragma unroll
    for (int k = 0; k < H_F; k++) {
        accl = fmaf(ag[k], sWl[k * HO_F + j], accl);
        accr = fmaf(hr[k], sWr[k * HO_F + j], accr);
    }
    float ident = bskip[j];
    const float* xr = x + (size_t)n * IN_F;
#pragma unroll
    for (int k = 0; k < IN_F; k++) ident = fmaf(xr[k], sWs[k * HO_F + j], ident);
    float acc = accl * inv + accr + b[j];
    float sc = g[j] * rsqrtf(v[j] + EPS_BN);
    float y = (acc - m[j]) * sc + be[j];
    d_h3[t] = fmaxf(y, 0.0f) + ident;
}

// ---------------- 11: classifier + log_softmax (warp per node) ----------------
__global__ void k_classifier(const float* __restrict__ Wc1, const float* __restrict__ bc1,
                             const float* __restrict__ Wc2, const float* __restrict__ bc2,
                             float* __restrict__ out) {
    __shared__ float sW1[32 * 32], sb1[32], sW2[64];
    for (int i = threadIdx.x; i < 32 * 32; i += blockDim.x) sW1[i] = Wc1[i];
    if (threadIdx.x < 32) sb1[threadIdx.x] = bc1[threadIdx.x];
    if (threadIdx.x < 64) sW2[threadIdx.x] = Wc2[threadIdx.x];
    __syncthreads();
    int gt = blockIdx.x * blockDim.x + threadIdx.x;
    int n = gt >> 5;
    int lane = threadIdx.x & 31;
    if (n >= N_NODES) return;
    float hv = d_h3[(size_t)n * 32 + lane];
    float s = sb1[lane];
#pragma unroll
    for (int k = 0; k < 32; k++) {
        float b = __shfl_sync(0xffffffffu, hv, k);
        s = fmaf(b, sW1[k * 32 + lane], s);
    }
    s = fmaxf(s, 0.0f);
    float p0 = s * sW2[lane * 2];
    float p1 = s * sW2[lane * 2 + 1];
#pragma unroll
    for (int o = 16; o; o >>= 1) {
        p0 += __shfl_down_sync(0xffffffffu, p0, o);
        p1 += __shfl_down_sync(0xffffffffu, p1, o);
    }
    if (lane == 0) {
        float l0 = p0 + bc2[0], l1 = p1 + bc2[1];
        float mx = fmaxf(l0, l1);
        float lse = mx + logf(__expf(l0 - mx) + __expf(l1 - mx));
        out[(size_t)n * 2]     = l0 - lse;
        out[(size_t)n * 2 + 1] = l1 - lse;
    }
}

// ---------------- launch ----------------
extern "C" void kernel_launch(void* const* d_in, const int* in_sizes, int n_in,
                              void* d_out, int out_size) {
    const float* x       = (const float*)d_in[0];
    const int*   ei      = (const int*)d_in[1];
    const float* W1l     = (const float*)d_in[2];
    const float* W1r     = (const float*)d_in[3];
    const float* b1      = (const float*)d_in[4];
    const float* g1      = (const float*)d_in[5];
    const float* be1     = (const float*)d_in[6];
    const float* m1      = (const float*)d_in[7];
    const float* v1      = (const float*)d_in[8];
    const float* Wg      = (const float*)d_in[9];
    const float* att_src = (const float*)d_in[10];
    const float* att_dst = (const float*)d_in[11];
    const float* bg      = (const float*)d_in[12];
    const float* g2      = (const float*)d_in[13];
    const float* be2     = (const float*)d_in[14];
    const float* m2      = (const float*)d_in[15];
    const float* v2      = (const float*)d_in[16];
    const float* W3l     = (const float*)d_in[17];
    const float* W3r     = (const float*)d_in[18];
    const float* b3      = (const float*)d_in[19];
    const float* g3      = (const float*)d_in[20];
    const float* be3     = (const float*)d_in[21];
    const float* m3      = (const float*)d_in[22];
    const float* v3      = (const float*)d_in[23];
    const float* Wskip   = (const float*)d_in[24];
    const float* bskip   = (const float*)d_in[25];
    const float* Wc1     = (const float*)d_in[26];
    const float* bc1     = (const float*)d_in[27];
    const float* Wc2     = (const float*)d_in[28];
    const float* bc2     = (const float*)d_in[29];
    float* out = (float*)d_out;

    const int TPB = 256;
    // init scratch: largest range is N*64 = 6.4M
    k_init<<<(N_NODES * H_F + TPB - 1) / TPB, TPB>>>();
    k_sage1_aggr<<<(E_EDGES + TPB - 1) / TPB, TPB>>>(x, ei);
    k_sage1_gemm<<<(N_NODES * H_F + TPB - 1) / TPB, TPB>>>(x, W1l, W1r, b1, g1, be1, m1, v1);
    k_gat_gemm<<<N_NODES / 4, TPB>>>(Wg);
    k_gat_att<<<N_NODES, 128>>>(att_src, att_dst);
    k_edge_max<<<(E_EDGES + TPB - 1) / TPB, TPB>>>(ei);
    k_edge_exp<<<(E_EDGES + TPB - 1) / TPB, TPB>>>(ei);
    k_edge_aggr<<<(E_EDGES * 32 + TPB - 1) / TPB, TPB>>>(ei);
    k_gat_epi<<<(N_NODES * H_F + TPB - 1) / TPB, TPB>>>(bg, g2, be2, m2, v2);
    k_sage3_aggr<<<(E_EDGES * 32 + TPB - 1) / TPB, TPB>>>(ei);
    k_sage3_gemm<<<(N_NODES * HO_F + TPB - 1) / TPB, TPB>>>(x, W3l, W3r, b3, g3, be3, m3, v3, Wskip, bskip);
    k_classifier<<<(N_NODES * 32 + TPB - 1) / TPB, TPB>>>(Wc1, bc1, Wc2, bc2, out);
}

// round 2
// speedup vs baseline: 1.5970x; 1.5970x over previous
#include <cuda_runtime.h>
#include <cuda_bf16.h>
#include <math.h>

#define N_NODES 100000
#define E_EDGES 1600000
#define IN_F 20
#define H_F 64
#define NHEADS 4
#define HO_F 32
#define EPS_BN 1e-5f

// ---------------- scratch (device globals; no allocation) ----------------
__device__ float d_deg[N_NODES];
__device__ float d_aggrx[N_NODES * IN_F];
__device__ float d_h1[N_NODES * H_F];
__device__ float d_hg[N_NODES * NHEADS * H_F];     // 102.4 MB
__device__ float d_asrc[N_NODES * NHEADS];
__device__ float d_adst[N_NODES * NHEADS];
__device__ float d_denom[N_NODES * NHEADS];
__device__ float d_gatout[N_NODES * H_F];          // sum over heads of alpha*feat
__device__ float d_h2[N_NODES * H_F];
__device__ float d_aggr2[N_NODES * H_F];
__device__ float d_h3[N_NODES * HO_F];

// ---------------- helpers ----------------
__device__ __forceinline__ void red_add_v4(float* addr, float4 v) {
    asm volatile("red.global.add.v4.f32 [%0], {%1,%2,%3,%4};"
                 :: "l"(addr), "f"(v.x), "f"(v.y), "f"(v.z), "f"(v.w) : "memory");
}

// ---------------- 0: init scratch ----------------
__global__ void k_init() {
    int i = blockIdx.x * blockDim.x + threadIdx.x;
    if (i < N_NODES) d_deg[i] = 0.0f;
    if (i < N_NODES * IN_F) d_aggrx[i] = 0.0f;
    if (i < N_NODES * NHEADS) d_denom[i] = 0.0f;
    if (i < N_NODES * H_F) { d_gatout[i] = 0.0f; d_aggr2[i] = 0.0f; }
}

// ---------------- 1: SAGE1 mean aggregation (edge) ----------------
__global__ void k_sage1_aggr(const float* __restrict__ x, const int* __restrict__ ei) {
    int e = blockIdx.x * blockDim.x + threadIdx.x;
    if (e >= E_EDGES) return;
    int s = ei[e];
    int d = ei[E_EDGES + e];
    atomicAdd(&d_deg[d], 1.0f);
    const float4* xs = (const float4*)(x + (size_t)s * IN_F);
    float* out = d_aggrx + (size_t)d * IN_F;
#pragma unroll
    for (int i = 0; i < IN_F / 4; i++) {
        float4 v = __ldg(&xs[i]);
        red_add_v4(out + i * 4, v);
    }
}

// ---------------- 2: SAGE1 GEMM + BN + ReLU ----------------
__global__ void k_sage1_gemm(const float* __restrict__ x,
                             const float* __restrict__ Wl, const float* __restrict__ Wr,
                             const float* __restrict__ b,
                             const float* __restrict__ g, const float* __restrict__ be,
                             const float* __restrict__ m, const float* __restrict__ v) {
    __shared__ float sWl[IN_F * H_F], sWr[IN_F * H_F];
    for (int i = threadIdx.x; i < IN_F * H_F; i += blockDim.x) { sWl[i] = Wl[i]; sWr[i] = Wr[i]; }
    __syncthreads();
    int t = blockIdx.x * blockDim.x + threadIdx.x;
    if (t >= N_NODES * H_F) return;
    int n = t >> 6, j = t & 63;
    float inv = 1.0f / fmaxf(d_deg[n], 1.0f);
    const float* ax = d_aggrx + (size_t)n * IN_F;
    const float* xr = x + (size_t)n * IN_F;
    float acc = b[j];
#pragma unroll
    for (int k = 0; k < IN_F; k++) {
        acc = fmaf(ax[k] * inv, sWl[k * H_F + j], acc);
        acc = fmaf(xr[k], sWr[k * H_F + j], acc);
    }
    float sc = g[j] * rsqrtf(v[j] + EPS_BN);
    float y = (acc - m[j]) * sc + be[j];
    d_h1[t] = fmaxf(y, 0.0f);
}

// ---------------- 3: GAT feature GEMM (register-blocked) + fused attention logits
// block = 256 threads, handles 32 nodes. thread (g = tid>>6 in [0,4), j = tid&63).
// thread computes hg[n, 4j..4j+3] for nodes n = blk*32 + g*8 + i, i in [0,8).
// W float4 loaded once per k and reused across 8 nodes -> 8x fewer L1 wavefronts.
// Attention: head = j>>4; a_src/a_dst partials reduced over 16-lane segments.
__global__ __launch_bounds__(256) void k_gat_gemm(const float* __restrict__ Wg,
                                                  const float* __restrict__ att_src,
                                                  const float* __restrict__ att_dst) {
    __shared__ float sh[32][64];
    int tid = threadIdx.x;
    int g = tid >> 6, j = tid & 63;
    int nbase = blockIdx.x * 32;
    // load 32x64 h1 tile (2048 floats; 256 threads x 2 float4)
    {
        const float4* src = (const float4*)(d_h1 + (size_t)nbase * H_F);
        float4* dst4 = (float4*)&sh[0][0];
        dst4[tid] = src[tid];
        dst4[tid + 256] = src[tid + 256];
    }
    __syncthreads();

    const float4* W4 = (const float4*)Wg;   // row k: W4[k*64 + j]
    float4 acc[8];
#pragma unroll
    for (int i = 0; i < 8; i++) acc[i] = make_float4(0.f, 0.f, 0.f, 0.f);

    const float4* sh4 = (const float4*)&sh[0][0];  // sh4[node*16 + k4]
    int nrow = g * 8;
#pragma unroll
    for (int k4 = 0; k4 < 16; k4++) {
        float4 w0 = __ldg(&W4[(k4 * 4 + 0) * 64 + j]);
        float4 w1 = __ldg(&W4[(k4 * 4 + 1) * 64 + j]);
        float4 w2 = __ldg(&W4[(k4 * 4 + 2) * 64 + j]);
        float4 w3 = __ldg(&W4[(k4 * 4 + 3) * 64 + j]);
#pragma unroll
        for (int i = 0; i < 8; i++) {
            float4 h = sh4[(nrow + i) * 16 + k4];
            acc[i].x = fmaf(h.x, w0.x, acc[i].x); acc[i].y = fmaf(h.x, w0.y, acc[i].y);
            acc[i].z = fmaf(h.x, w0.z, acc[i].z); acc[i].w = fmaf(h.x, w0.w, acc[i].w);
            acc[i].x = fmaf(h.y, w1.x, acc[i].x); acc[i].y = fmaf(h.y, w1.y, acc[i].y);
            acc[i].z = fmaf(h.y, w1.z, acc[i].z); acc[i].w = fmaf(h.y, w1.w, acc[i].w);
            acc[i].x = fmaf(h.z, w2.x, acc[i].x); acc[i].y = fmaf(h.z, w2.y, acc[i].y);
            acc[i].z = fmaf(h.z, w2.z, acc[i].z); acc[i].w = fmaf(h.z, w2.w, acc[i].w);
            acc[i].x = fmaf(h.w, w3.x, acc[i].x); acc[i].y = fmaf(h.w, w3.y, acc[i].y);
            acc[i].z = fmaf(h.w, w3.z, acc[i].z); acc[i].w = fmaf(h.w, w3.w, acc[i].w);
        }
    }

    // write hg
    float4* hg4 = (float4*)d_hg;
#pragma unroll
    for (int i = 0; i < 8; i++) {
        int n = nbase + nrow + i;
        hg4[(size_t)n * 64 + j] = acc[i];
    }

    // fused attention logits: head = j>>4, dfeat base = 4*(j&15)
    int head = j >> 4;
    int db = 4 * (j & 15);
    float was0 = __ldg(&att_src[head * 64 + db + 0]);
    float was1 = __ldg(&att_src[head * 64 + db + 1]);
    float was2 = __ldg(&att_src[head * 64 + db + 2]);
    float was3 = __ldg(&att_src[head * 64 + db + 3]);
    float wad0 = __ldg(&att_dst[head * 64 + db + 0]);
    float wad1 = __ldg(&att_dst[head * 64 + db + 1]);
    float wad2 = __ldg(&att_dst[head * 64 + db + 2]);
    float wad3 = __ldg(&att_dst[head * 64 + db + 3]);
#pragma unroll
    for (int i = 0; i < 8; i++) {
        float ps = acc[i].x * was0 + acc[i].y * was1 + acc[i].z * was2 + acc[i].w * was3;
        float pd = acc[i].x * wad0 + acc[i].y * wad1 + acc[i].z * wad2 + acc[i].w * wad3;
#pragma unroll
        for (int o = 8; o; o >>= 1) {
            ps += __shfl_down_sync(0xffffffffu, ps, o, 16);
            pd += __shfl_down_sync(0xffffffffu, pd, o, 16);
        }
        if ((j & 15) == 0) {
            int n = nbase + nrow + i;
            d_asrc[n * NHEADS + head] = ps;
            d_adst[n * NHEADS + head] = pd;
        }
    }
}

// ---------------- 4: edge pass A: exp + denom (no max; logits are O(1)) ----------
__global__ void k_edge_denom(const int* __restrict__ ei) {
    int e = blockIdx.x * blockDim.x + threadIdx.x;
    if (e >= E_EDGES) return;
    int s = ei[e], d = ei[E_EDGES + e];
    float4 as = *(const float4*)&d_asrc[s * 4];
    float4 ad = *(const float4*)&d_adst[d * 4];
    float a; float4 ex;
    a = as.x + ad.x; a = a > 0.f ? a : 0.2f * a; ex.x = __expf(a);
    a = as.y + ad.y; a = a > 0.f ? a : 0.2f * a; ex.y = __expf(a);
    a = as.z + ad.z; a = a > 0.f ? a : 0.2f * a; ex.z = __expf(a);
    a = as.w + ad.w; a = a > 0.f ? a : 0.2f * a; ex.w = __expf(a);
    red_add_v4(&d_denom[d * 4], ex);
}

// ---------------- 5: edge pass B: alpha-weighted aggregation (16 thr/edge) ------
// accumulates sum over heads of alpha_h * hg[src, h*64 + :] into d_gatout[dst*64+:]
__global__ void k_edge_aggr(const int* __restrict__ ei) {
    int gt = blockIdx.x * blockDim.x + threadIdx.x;
    int e = gt >> 4;
    if (e >= E_EDGES) return;
    int lane = threadIdx.x & 31;
    int t16 = lane & 15;
    int s = ei[e], d = ei[E_EDGES + e];
    float alpha = 0.0f;
    if (t16 < 4) {
        float a = d_asrc[s * 4 + t16] + d_adst[d * 4 + t16];
        a = a > 0.f ? a : 0.2f * a;
        alpha = __expf(a) / (d_denom[d * 4 + t16] + 1e-16f);
    }
    int base = lane & 16;
    float a0 = __shfl_sync(0xffffffffu, alpha, base + 0);
    float a1 = __shfl_sync(0xffffffffu, alpha, base + 1);
    float a2 = __shfl_sync(0xffffffffu, alpha, base + 2);
    float a3 = __shfl_sync(0xffffffffu, alpha, base + 3);
    const float4* hp = (const float4*)(d_hg + (size_t)s * 256);
    float4 v0 = __ldg(&hp[t16]);
    float4 v1 = __ldg(&hp[16 + t16]);
    float4 v2 = __ldg(&hp[32 + t16]);
    float4 v3 = __ldg(&hp[48 + t16]);
    float4 o;
    o.x = a0 * v0.x + a1 * v1.x + a2 * v2.x + a3 * v3.x;
    o.y = a0 * v0.y + a1 * v1.y + a2 * v2.y + a3 * v3.y;
    o.z = a0 * v0.z + a1 * v1.z + a2 * v2.z + a3 * v3.z;
    o.w = a0 * v0.w + a1 * v1.w + a2 * v2.w + a3 * v3.w;
    red_add_v4(d_gatout + (size_t)d * 64 + t16 * 4, o);
}

// ---------------- 6: GAT epilogue: mean over heads + bias + BN + ReLU --------
__global__ void k_gat_epi(const float* __restrict__ bg,
                          const float* __restrict__ g, const float* __restrict__ be,
                          const float* __restrict__ m, const float* __restrict__ v) {
    int t = blockIdx.x * blockDim.x + threadIdx.x;
    if (t >= N_NODES * H_F) return;
    int j = t & 63;
    float y = d_gatout[t] * 0.25f + bg[j];
    float sc = g[j] * rsqrtf(v[j] + EPS_BN);
    y = (y - m[j]) * sc + be[j];
    d_h2[t] = fmaxf(y, 0.0f);
}

// ---------------- 7: SAGE3 aggregation (16 thr/edge, red.v4) ----------------
__global__ void k_sage3_aggr(const int* __restrict__ ei) {
    int gt = blockIdx.x * blockDim.x + threadIdx.x;
    int e = gt >> 4;
    if (e >= E_EDGES) return;
    int t16 = threadIdx.x & 15;
    int s = ei[e], d = ei[E_EDGES + e];
    float4 v = __ldg(&((const float4*)(d_h2 + (size_t)s * H_F))[t16]);
    red_add_v4(d_aggr2 + (size_t)d * H_F + t16 * 4, v);
}

// ---------------- 8: SAGE3 GEMM + BN + ReLU + skip ----------------
__global__ void k_sage3_gemm(const float* __restrict__ x,
                             const float* __restrict__ Wl, const float* __restrict__ Wr,
                             const float* __restrict__ b,
                             const float* __restrict__ g, const float* __restrict__ be,
                             const float* __restrict__ m, const float* __restrict__ v,
                             const float* __restrict__ Wskip, const float* __restrict__ bskip) {
    __shared__ float sWl[H_F * HO_F], sWr[H_F * HO_F], sWs[IN_F * HO_F];
    for (int i = threadIdx.x; i < H_F * HO_F; i += blockDim.x) { sWl[i] = Wl[i]; sWr[i] = Wr[i]; }
    for (int i = threadIdx.x; i < IN_F * HO_F; i += blockDim.x) sWs[i] = Wskip[i];
    __syncthreads();
    int t = blockIdx.x * blockDim.x + threadIdx.x;
    if (t >= N_NODES * HO_F) return;
    int n = t >> 5, j = t & 31;
    float inv = 1.0f / fmaxf(d_deg[n], 1.0f);
    const float* ag = d_aggr2 + (size_t)n * H_F;
    const float* hr = d_h2 + (size_t)n * H_F;
    float accl = 0.0f, accr = 0.0f;
#pragma unroll
    for (int k = 0; k < H_F; k++) {
        accl = fmaf(ag[k], sWl[k * HO_F + j], accl);
        accr = fmaf(hr[k], sWr[k * HO_F + j], accr);
    }
    float ident = bskip[j];
    const float* xr = x + (size_t)n * IN_F;
#pragma unroll
    for (int k = 0; k < IN_F; k++) ident = fmaf(xr[k], sWs[k * HO_F + j], ident);
    float acc = accl * inv + accr + b[j];
    float sc = g[j] * rsqrtf(v[j] + EPS_BN);
    float y = (acc - m[j]) * sc + be[j];
    d_h3[t] = fmaxf(y, 0.0f) + ident;
}

// ---------------- 9: classifier + log_softmax (warp per node) ----------------
__global__ void k_classifier(const float* __restrict__ Wc1, const float* __restrict__ bc1,
                             const float* __restrict__ Wc2, const float* __restrict__ bc2,
                             float* __restrict__ out) {
    __shared__ float sW1[32 * 32], sb1[32], sW2[64];
    for (int i = threadIdx.x; i < 32 * 32; i += blockDim.x) sW1[i] = Wc1[i];
    if (threadIdx.x < 32) sb1[threadIdx.x] = bc1[threadIdx.x];
    if (threadIdx.x < 64) sW2[threadIdx.x] = Wc2[threadIdx.x];
    __syncthreads();
    int gt = blockIdx.x * blockDim.x + threadIdx.x;
    int n = gt >> 5;
    int lane = threadIdx.x & 31;
    if (n >= N_NODES) return;
    float hv = d_h3[(size_t)n * 32 + lane];
    float s = sb1[lane];
#pragma unroll
    for (int k = 0; k < 32; k++) {
        float b = __shfl_sync(0xffffffffu, hv, k);
        s = fmaf(b, sW1[k * 32 + lane], s);
    }
    s = fmaxf(s, 0.0f);
    float p0 = s * sW2[lane * 2];
    float p1 = s * sW2[lane * 2 + 1];
#pragma unroll
    for (int o = 16; o; o >>= 1) {
        p0 += __shfl_down_sync(0xffffffffu, p0, o);
        p1 += __shfl_down_sync(0xffffffffu, p1, o);
    }
    if (lane == 0) {
        float l0 = p0 + bc2[0], l1 = p1 + bc2[1];
        float mx = fmaxf(l0, l1);
        float lse = mx + logf(__expf(l0 - mx) + __expf(l1 - mx));
        out[(size_t)n * 2]     = l0 - lse;
        out[(size_t)n * 2 + 1] = l1 - lse;
    }
}

// ---------------- launch ----------------
extern "C" void kernel_launch(void* const* d_in, const int* in_sizes, int n_in,
                              void* d_out, int out_size) {
    const float* x       = (const float*)d_in[0];
    const int*   ei      = (const int*)d_in[1];
    const float* W1l     = (const float*)d_in[2];
    const float* W1r     = (const float*)d_in[3];
    const float* b1      = (const float*)d_in[4];
    const float* g1      = (const float*)d_in[5];
    const float* be1     = (const float*)d_in[6];
    const float* m1      = (const float*)d_in[7];
    const float* v1      = (const float*)d_in[8];
    const float* Wg      = (const float*)d_in[9];
    const float* att_src = (const float*)d_in[10];
    const float* att_dst = (const float*)d_in[11];
    const float* bg      = (const float*)d_in[12];
    const float* g2      = (const float*)d_in[13];
    const float* be2     = (const float*)d_in[14];
    const float* m2      = (const float*)d_in[15];
    const float* v2      = (const float*)d_in[16];
    const float* W3l     = (const float*)d_in[17];
    const float* W3r     = (const float*)d_in[18];
    const float* b3      = (const float*)d_in[19];
    const float* g3      = (const float*)d_in[20];
    const float* be3     = (const float*)d_in[21];
    const float* m3      = (const float*)d_in[22];
    const float* v3      = (const float*)d_in[23];
    const float* Wskip   = (const float*)d_in[24];
    const float* bskip   = (const float*)d_in[25];
    const float* Wc1     = (const float*)d_in[26];
    const float* bc1     = (const float*)d_in[27];
    const float* Wc2     = (const float*)d_in[28];
    const float* bc2     = (const float*)d_in[29];
    float* out = (float*)d_out;

    const int TPB = 256;
    k_init<<<(N_NODES * H_F + TPB - 1) / TPB, TPB>>>();
    k_sage1_aggr<<<(E_EDGES + TPB - 1) / TPB, TPB>>>(x, ei);
    k_sage1_gemm<<<(N_NODES * H_F + TPB - 1) / TPB, TPB>>>(x, W1l, W1r, b1, g1, be1, m1, v1);
    k_gat_gemm<<<N_NODES / 32, TPB>>>(Wg, att_src, att_dst);
    k_edge_denom<<<(E_EDGES + TPB - 1) / TPB, TPB>>>(ei);
    k_edge_aggr<<<(E_EDGES * 16 + TPB - 1) / TPB, TPB>>>(ei);
    k_gat_epi<<<(N_NODES * H_F + TPB - 1) / TPB, TPB>>>(bg, g2, be2, m2, v2);
    k_sage3_aggr<<<(E_EDGES * 16 + TPB - 1) / TPB, TPB>>>(ei);
    k_sage3_gemm<<<(N_NODES * HO_F + TPB - 1) / TPB, TPB>>>(x, W3l, W3r, b3, g3, be3, m3, v3, Wskip, bskip);
    k_classifier<<<(N_NODES * 32 + TPB - 1) / TPB, TPB>>>(Wc1, bc1, Wc2, bc2, out);
}

// round 3
// speedup vs baseline: 1.9449x; 1.2178x over previous
#include <cuda_runtime.h>
#include <cuda_bf16.h>
#include <math.h>

#define N_NODES 100000
#define E_EDGES 1600000
#define IN_F 20
#define H_F 64
#define NHEADS 4
#define HO_F 32
#define EPS_BN 1e-5f
#define SCAN_B 512
#define NB_SCAN ((N_NODES + SCAN_B - 1) / SCAN_B)   // 196
#define CAP 128                                     // smem exp-cache depth per node

// ---------------- scratch (device globals; no allocation) ----------------
__device__ int   d_cnt[N_NODES];
__device__ int   d_rowptr[N_NODES + 1];
__device__ int   d_cursor[N_NODES];
__device__ int   d_bsum[NB_SCAN];
__device__ int   d_bsum2[NB_SCAN];
__device__ int   d_csr_src[E_EDGES];
__device__ float d_aggrx[N_NODES * IN_F];           // mean-aggregated x
__device__ float d_h1[N_NODES * H_F];
__device__ __nv_bfloat16 d_hgb[N_NODES * NHEADS * H_F];  // 51.2 MB (L2-resident)
__device__ float d_asrc[N_NODES * NHEADS];
__device__ float d_adst[N_NODES * NHEADS];
__device__ float d_h2[N_NODES * H_F];
__device__ float d_aggr2[N_NODES * H_F];            // mean-aggregated h2
__device__ float d_h3[N_NODES * HO_F];

// ---------------- CSR build ----------------
__global__ void k_init() {
    int i = blockIdx.x * blockDim.x + threadIdx.x;
    if (i < N_NODES) d_cnt[i] = 0;
}
__global__ void k_count(const int* __restrict__ ei) {
    int e = blockIdx.x * blockDim.x + threadIdx.x;
    if (e >= E_EDGES) return;
    atomicAdd(&d_cnt[ei[E_EDGES + e]], 1);
}
__global__ void k_scan1() {
    __shared__ int sd[SCAN_B];
    int tid = threadIdx.x;
    int i = blockIdx.x * SCAN_B + tid;
    int v = (i < N_NODES) ? d_cnt[i] : 0;
    sd[tid] = v;
    __syncthreads();
    for (int o = 1; o < SCAN_B; o <<= 1) {
        int t = (tid >= o) ? sd[tid - o] : 0;
        __syncthreads();
        sd[tid] += t;
        __syncthreads();
    }
    if (i < N_NODES) d_rowptr[i] = sd[tid] - v;      // exclusive within block
    if (tid == SCAN_B - 1) d_bsum[blockIdx.x] = sd[tid];
}
__global__ void k_scan2() {
    __shared__ int sd[256];
    int tid = threadIdx.x;
    int v = (tid < NB_SCAN) ? d_bsum[tid] : 0;
    sd[tid] = v;
    __syncthreads();
    for (int o = 1; o < 256; o <<= 1) {
        int t = (tid >= o) ? sd[tid - o] : 0;
        __syncthreads();
        sd[tid] += t;
        __syncthreads();
    }
    if (tid < NB_SCAN) d_bsum2[tid] = sd[tid] - v;   // exclusive block offsets
    if (tid == 0) d_rowptr[N_NODES] = E_EDGES;
}
__global__ void k_scan3() {
    int i = blockIdx.x * SCAN_B + threadIdx.x;
    if (i < N_NODES) {
        int r = d_rowptr[i] + d_bsum2[blockIdx.x];
        d_rowptr[i] = r;
        d_cursor[i] = r;
    }
}
__global__ void k_scatter(const int* __restrict__ ei) {
    int e = blockIdx.x * blockDim.x + threadIdx.x;
    if (e >= E_EDGES) return;
    int s = ei[e], d = ei[E_EDGES + e];
    int pos = atomicAdd(&d_cursor[d], 1);
    d_csr_src[pos] = s;
}

// ---------------- SAGE1 mean aggregation (CSR, warp per node) ----------------
__global__ __launch_bounds__(256) void k_sage1_csr(const float* __restrict__ x) {
    int n = blockIdx.x * 8 + (threadIdx.x >> 5);
    int lane = threadIdx.x & 31;
    if (n >= N_NODES) return;
    int row = d_rowptr[n];
    int deg = d_rowptr[n + 1] - row;
    float acc = 0.0f;
    for (int c = 0; c < deg; c += 32) {
        int idx = c + lane;
        int s_l = (idx < deg) ? __ldg(&d_csr_src[row + idx]) : 0;
        int kmax = min(32, deg - c);
        for (int i = 0; i < kmax; i++) {
            int s = __shfl_sync(0xffffffffu, s_l, i);
            if (lane < IN_F) acc += __ldg(&x[(size_t)s * IN_F + lane]);
        }
    }
    float inv = 1.0f / fmaxf((float)deg, 1.0f);
    if (lane < IN_F) d_aggrx[(size_t)n * IN_F + lane] = acc * inv;
}

// ---------------- SAGE1 GEMM + BN + ReLU ----------------
__global__ void k_sage1_gemm(const float* __restrict__ x,
                             const float* __restrict__ Wl, const float* __restrict__ Wr,
                             const float* __restrict__ b,
                             const float* __restrict__ g, const float* __restrict__ be,
                             const float* __restrict__ m, const float* __restrict__ v) {
    __shared__ float sWl[IN_F * H_F], sWr[IN_F * H_F];
    for (int i = threadIdx.x; i < IN_F * H_F; i += blockDim.x) { sWl[i] = Wl[i]; sWr[i] = Wr[i]; }
    __syncthreads();
    int t = blockIdx.x * blockDim.x + threadIdx.x;
    if (t >= N_NODES * H_F) return;
    int n = t >> 6, j = t & 63;
    const float* ax = d_aggrx + (size_t)n * IN_F;
    const float* xr = x + (size_t)n * IN_F;
    float acc = b[j];
#pragma unroll
    for (int k = 0; k < IN_F; k++) {
        acc = fmaf(ax[k], sWl[k * H_F + j], acc);
        acc = fmaf(xr[k], sWr[k * H_F + j], acc);
    }
    float sc = g[j] * rsqrtf(v[j] + EPS_BN);
    float y = (acc - m[j]) * sc + be[j];
    d_h1[t] = fmaxf(y, 0.0f);
}

// ---------------- GAT feature GEMM (register-blocked, bf16 out) + att logits ----
__global__ __launch_bounds__(256) void k_gat_gemm(const float* __restrict__ Wg,
                                                  const float* __restrict__ att_src,
                                                  const float* __restrict__ att_dst) {
    __shared__ float sh[32][64];
    int tid = threadIdx.x;
    int g = tid >> 6, j = tid & 63;
    int nbase = blockIdx.x * 32;
    {
        const float4* src = (const float4*)(d_h1 + (size_t)nbase * H_F);
        float4* dst4 = (float4*)&sh[0][0];
        dst4[tid] = src[tid];
        dst4[tid + 256] = src[tid + 256];
    }
    __syncthreads();

    const float4* W4 = (const float4*)Wg;
    float4 acc[8];
#pragma unroll
    for (int i = 0; i < 8; i++) acc[i] = make_float4(0.f, 0.f, 0.f, 0.f);

    const float4* sh4 = (const float4*)&sh[0][0];
    int nrow = g * 8;
#pragma unroll
    for (int k4 = 0; k4 < 16; k4++) {
        float4 w0 = __ldg(&W4[(k4 * 4 + 0) * 64 + j]);
        float4 w1 = __ldg(&W4[(k4 * 4 + 1) * 64 + j]);
        float4 w2 = __ldg(&W4[(k4 * 4 + 2) * 64 + j]);
        float4 w3 = __ldg(&W4[(k4 * 4 + 3) * 64 + j]);
#pragma unroll
        for (int i = 0; i < 8; i++) {
            float4 h = sh4[(nrow + i) * 16 + k4];
            acc[i].x = fmaf(h.x, w0.x, acc[i].x); acc[i].y = fmaf(h.x, w0.y, acc[i].y);
            acc[i].z = fmaf(h.x, w0.z, acc[i].z); acc[i].w = fmaf(h.x, w0.w, acc[i].w);
            acc[i].x = fmaf(h.y, w1.x, acc[i].x); acc[i].y = fmaf(h.y, w1.y, acc[i].y);
            acc[i].z = fmaf(h.y, w1.z, acc[i].z); acc[i].w = fmaf(h.y, w1.w, acc[i].w);
            acc[i].x = fmaf(h.z, w2.x, acc[i].x); acc[i].y = fmaf(h.z, w2.y, acc[i].y);
            acc[i].z = fmaf(h.z, w2.z, acc[i].z); acc[i].w = fmaf(h.z, w2.w, acc[i].w);
            acc[i].x = fmaf(h.w, w3.x, acc[i].x); acc[i].y = fmaf(h.w, w3.y, acc[i].y);
            acc[i].z = fmaf(h.w, w3.z, acc[i].z); acc[i].w = fmaf(h.w, w3.w, acc[i].w);
        }
    }

    // write hg in bf16
#pragma unroll
    for (int i = 0; i < 8; i++) {
        int n = nbase + nrow + i;
        __nv_bfloat162 p0 = __float22bfloat162_rn(make_float2(acc[i].x, acc[i].y));
        __nv_bfloat162 p1 = __float22bfloat162_rn(make_float2(acc[i].z, acc[i].w));
        uint2 u;
        u.x = *reinterpret_cast<unsigned int*>(&p0);
        u.y = *reinterpret_cast<unsigned int*>(&p1);
        *reinterpret_cast<uint2*>(d_hgb + (size_t)n * 256 + j * 4) = u;
    }

    // fused attention logits
    int head = j >> 4;
    int db = 4 * (j & 15);
    float was0 = __ldg(&att_src[head * 64 + db + 0]);
    float was1 = __ldg(&att_src[head * 64 + db + 1]);
    float was2 = __ldg(&att_src[head * 64 + db + 2]);
    float was3 = __ldg(&att_src[head * 64 + db + 3]);
    float wad0 = __ldg(&att_dst[head * 64 + db + 0]);
    float wad1 = __ldg(&att_dst[head * 64 + db + 1]);
    float wad2 = __ldg(&att_dst[head * 64 + db + 2]);
    float wad3 = __ldg(&att_dst[head * 64 + db + 3]);
#pragma unroll
    for (int i = 0; i < 8; i++) {
        float ps = acc[i].x * was0 + acc[i].y * was1 + acc[i].z * was2 + acc[i].w * was3;
        float pd = acc[i].x * wad0 + acc[i].y * wad1 + acc[i].z * wad2 + acc[i].w * wad3;
#pragma unroll
        for (int o = 8; o; o >>= 1) {
            ps += __shfl_down_sync(0xffffffffu, ps, o, 16);
            pd += __shfl_down_sync(0xffffffffu, pd, o, 16);
        }
        if ((j & 15) == 0) {
            int n = nbase + nrow + i;
            d_asrc[n * NHEADS + head] = ps;
            d_adst[n * NHEADS + head] = pd;
        }
    }
}

// ---------------- GAT CSR aggregation + fused epilogue (warp per node) ---------
// phase1: softmax denominator per head (exp cached in smem up to CAP edges)
// phase2: alpha-weighted sum over heads of bf16 hg rows, BN+ReLU, write h2
__global__ __launch_bounds__(256) void k_gat_csr(const float* __restrict__ bg,
                                                 const float* __restrict__ g2,
                                                 const float* __restrict__ be2,
                                                 const float* __restrict__ m2,
                                                 const float* __restrict__ v2) {
    __shared__ float sExp[8][CAP * 4];
    int w = threadIdx.x >> 5;
    int lane = threadIdx.x & 31;
    int n = blockIdx.x * 8 + w;
    if (n >= N_NODES) return;
    int row = d_rowptr[n];
    int deg = d_rowptr[n + 1] - row;

    float4 ad = *(const float4*)&d_adst[n * 4];

    // phase 1: denominators
    float4 den = make_float4(0.f, 0.f, 0.f, 0.f);
    for (int c = 0; c < deg; c += 32) {
        int idx = c + lane;
        bool val = idx < deg;
        int s = val ? __ldg(&d_csr_src[row + idx]) : 0;
        float4 a = *(const float4*)&d_asrc[s * 4];
        float4 ex;
        float t;
        t = a.x + ad.x; t = t > 0.f ? t : 0.2f * t; ex.x = __expf(t);
        t = a.y + ad.y; t = t > 0.f ? t : 0.2f * t; ex.y = __expf(t);
        t = a.z + ad.z; t = t > 0.f ? t : 0.2f * t; ex.z = __expf(t);
        t = a.w + ad.w; t = t > 0.f ? t : 0.2f * t; ex.w = __expf(t);
        if (val) {
            den.x += ex.x; den.y += ex.y; den.z += ex.z; den.w += ex.w;
            if (idx < CAP) *(float4*)&sExp[w][idx * 4] = ex;
        }
    }
#pragma unroll
    for (int o = 16; o; o >>= 1) {
        den.x += __shfl_xor_sync(0xffffffffu, den.x, o);
        den.y += __shfl_xor_sync(0xffffffffu, den.y, o);
        den.z += __shfl_xor_sync(0xffffffffu, den.z, o);
        den.w += __shfl_xor_sync(0xffffffffu, den.w, o);
    }

    int head = lane >> 3;
    float denH = head == 0 ? den.x : head == 1 ? den.y : head == 2 ? den.z : den.w;
    float adH  = head == 0 ? ad.x  : head == 1 ? ad.y  : head == 2 ? ad.z  : ad.w;
    float invd = 1.0f / (denH + 1e-16f);

    // phase 2
    float acc[8];
#pragma unroll
    for (int q = 0; q < 8; q++) acc[q] = 0.0f;
    const uint4* hg4 = (const uint4*)d_hgb;   // 8 bf16 per uint4; row = 32 uint4
    for (int c = 0; c < deg; c += 32) {
        int idx = c + lane;
        int s_l = (idx < deg) ? __ldg(&d_csr_src[row + idx]) : 0;
        int kmax = min(32, deg - c);
        for (int i = 0; i < kmax; i++) {
            int s = __shfl_sync(0xffffffffu, s_l, i);
            int eidx = c + i;
            float ex;
            if (eidx < CAP) {
                ex = sExp[w][eidx * 4 + head];
            } else {
                float a = __ldg(&d_asrc[s * 4 + head]) + adH;
                a = a > 0.f ? a : 0.2f * a;
                ex = __expf(a);
            }
            float alpha = ex * invd;
            uint4 vv = __ldg(&hg4[(size_t)s * 32 + lane]);
            const __nv_bfloat162* bp = (const __nv_bfloat162*)&vv;
#pragma unroll
            for (int q = 0; q < 4; q++) {
                float2 f = __bfloat1622float2(bp[q]);
                acc[q * 2 + 0] = fmaf(alpha, f.x, acc[q * 2 + 0]);
                acc[q * 2 + 1] = fmaf(alpha, f.y, acc[q * 2 + 1]);
            }
        }
    }
    // reduce over heads: lanes 0..7 end with feats lane*8..lane*8+7
#pragma unroll
    for (int q = 0; q < 8; q++) {
        acc[q] += __shfl_xor_sync(0xffffffffu, acc[q], 8);
        acc[q] += __shfl_xor_sync(0xffffffffu, acc[q], 16);
    }
    if (lane < 8) {
#pragma unroll
        for (int q = 0; q < 8; q++) {
            int j = lane * 8 + q;
            float sc = __ldg(&g2[j]) * rsqrtf(__ldg(&v2[j]) + EPS_BN);
            float y = (acc[q] * 0.25f + __ldg(&bg[j]) - __ldg(&m2[j])) * sc + __ldg(&be2[j]);
            d_h2[(size_t)n * H_F + j] = fmaxf(y, 0.0f);
        }
    }
}

// ---------------- SAGE3 mean aggregation (CSR, warp per node, 2 edges/iter) ----
__global__ __launch_bounds__(256) void k_sage3_csr() {
    int n = blockIdx.x * 8 + (threadIdx.x >> 5);
    int lane = threadIdx.x & 31;
    if (n >= N_NODES) return;
    int row = d_rowptr[n];
    int deg = d_rowptr[n + 1] - row;
    int half = lane >> 4;
    int f = lane & 15;
    float4 acc = make_float4(0.f, 0.f, 0.f, 0.f);
    const float4* h24 = (const float4*)d_h2;   // row = 16 float4
    for (int c = 0; c < deg; c += 32) {
        int idx = c + lane;
        int s_l = (idx < deg) ? __ldg(&d_csr_src[row + idx]) : 0;
        int kmax = min(32, deg - c);
        for (int i = 0; i < kmax; i += 2) {
            int e = i + half;
            int s = __shfl_sync(0xffffffffu, s_l, e & 31);
            if (e < kmax) {
                float4 vv = __ldg(&h24[(size_t)s * 16 + f]);
                acc.x += vv.x; acc.y += vv.y; acc.z += vv.z; acc.w += vv.w;
            }
        }
    }
    acc.x += __shfl_xor_sync(0xffffffffu, acc.x, 16);
    acc.y += __shfl_xor_sync(0xffffffffu, acc.y, 16);
    acc.z += __shfl_xor_sync(0xffffffffu, acc.z, 16);
    acc.w += __shfl_xor_sync(0xffffffffu, acc.w, 16);
    if (lane < 16) {
        float inv = 1.0f / fmaxf((float)deg, 1.0f);
        acc.x *= inv; acc.y *= inv; acc.z *= inv; acc.w *= inv;
        ((float4*)d_aggr2)[(size_t)n * 16 + f] = acc;
    }
}

// ---------------- SAGE3 GEMM + BN + ReLU + skip ----------------
__global__ void k_sage3_gemm(const float* __restrict__ x,
                             const float* __restrict__ Wl, const float* __restrict__ Wr,
                             const float* __restrict__ b,
                             const float* __restrict__ g, const float* __restrict__ be,
                             const float* __restrict__ m, const float* __restrict__ v,
                             const float* __restrict__ Wskip, const float* __restrict__ bskip) {
    __shared__ float sWl[H_F * HO_F], sWr[H_F * HO_F], sWs[IN_F * HO_F];
    for (int i = threadIdx.x; i < H_F * HO_F; i += blockDim.x) { sWl[i] = Wl[i]; sWr[i] = Wr[i]; }
    for (int i = threadIdx.x; i < IN_F * HO_F; i += blockDim.x) sWs[i] = Wskip[i];
    __syncthreads();
    int t = blockIdx.x * blockDim.x + threadIdx.x;
    if (t >= N_NODES * HO_F) return;
    int n = t >> 5, j = t & 31;
    const float* ag = d_aggr2 + (size_t)n * H_F;
    const float* hr = d_h2 + (size_t)n * H_F;
    float acc = b[j];
#pragma unroll
    for (int k = 0; k < H_F; k++) {
        acc = fmaf(ag[k], sWl[k * HO_F + j], acc);
        acc = fmaf(hr[k], sWr[k * HO_F + j], acc);
    }
    float ident = bskip[j];
    const float* xr = x + (size_t)n * IN_F;
#pragma unroll
    for (int k = 0; k < IN_F; k++) ident = fmaf(xr[k], sWs[k * HO_F + j], ident);
    float sc = g[j] * rsqrtf(v[j] + EPS_BN);
    float y = (acc - m[j]) * sc + be[j];
    d_h3[t] = fmaxf(y, 0.0f) + ident;
}

// ---------------- classifier + log_softmax (warp per node) ----------------
__global__ void k_classifier(const float* __restrict__ Wc1, const float* __restrict__ bc1,
                             const float* __restrict__ Wc2, const float* __restrict__ bc2,
                             float* __restrict__ out) {
    __shared__ float sW1[32 * 32], sb1[32], sW2[64];
    for (int i = threadIdx.x; i < 32 * 32; i += blockDim.x) sW1[i] = Wc1[i];
    if (threadIdx.x < 32) sb1[threadIdx.x] = bc1[threadIdx.x];
    if (threadIdx.x < 64) sW2[threadIdx.x] = Wc2[threadIdx.x];
    __syncthreads();
    int gt = blockIdx.x * blockDim.x + threadIdx.x;
    int n = gt >> 5;
    int lane = threadIdx.x & 31;
    if (n >= N_NODES) return;
    float hv = d_h3[(size_t)n * 32 + lane];
    float s = sb1[lane];
#pragma unroll
    for (int k = 0; k < 32; k++) {
        float b = __shfl_sync(0xffffffffu, hv, k);
        s = fmaf(b, sW1[k * 32 + lane], s);
    }
    s = fmaxf(s, 0.0f);
    float p0 = s * sW2[lane * 2];
    float p1 = s * sW2[lane * 2 + 1];
#pragma unroll
    for (int o = 16; o; o >>= 1) {
        p0 += __shfl_down_sync(0xffffffffu, p0, o);
        p1 += __shfl_down_sync(0xffffffffu, p1, o);
    }
    if (lane == 0) {
        float l0 = p0 + bc2[0], l1 = p1 + bc2[1];
        float mx = fmaxf(l0, l1);
        float lse = mx + logf(__expf(l0 - mx) + __expf(l1 - mx));
        out[(size_t)n * 2]     = l0 - lse;
        out[(size_t)n * 2 + 1] = l1 - lse;
    }
}

// ---------------- launch ----------------
extern "C" void kernel_launch(void* const* d_in, const int* in_sizes, int n_in,
                              void* d_out, int out_size) {
    const float* x       = (const float*)d_in[0];
    const int*   ei      = (const int*)d_in[1];
    const float* W1l     = (const float*)d_in[2];
    const float* W1r     = (const float*)d_in[3];
    const float* b1      = (const float*)d_in[4];
    const float* g1      = (const float*)d_in[5];
    const float* be1     = (const float*)d_in[6];
    const float* m1      = (const float*)d_in[7];
    const float* v1      = (const float*)d_in[8];
    const float* Wg      = (const float*)d_in[9];
    const float* att_src = (const float*)d_in[10];
    const float* att_dst = (const float*)d_in[11];
    const float* bg      = (const float*)d_in[12];
    const float* g2      = (const float*)d_in[13];
    const float* be2     = (const float*)d_in[14];
    const float* m2      = (const float*)d_in[15];
    const float* v2      = (const float*)d_in[16];
    const float* W3l     = (const float*)d_in[17];
    const float* W3r     = (const float*)d_in[18];
    const float* b3      = (const float*)d_in[19];
    const float* g3      = (const float*)d_in[20];
    const float* be3     = (const float*)d_in[21];
    const float* m3      = (const float*)d_in[22];
    const float* v3      = (const float*)d_in[23];
    const float* Wskip   = (const float*)d_in[24];
    const float* bskip   = (const float*)d_in[25];
    const float* Wc1     = (const float*)d_in[26];
    const float* bc1     = (const float*)d_in[27];
    const float* Wc2     = (const float*)d_in[28];
    const float* bc2     = (const float*)d_in[29];
    float* out = (float*)d_out;

    const int TPB = 256;
    // CSR build
    k_init<<<(N_NODES + TPB - 1) / TPB, TPB>>>();
    k_count<<<(E_EDGES + TPB - 1) / TPB, TPB>>>(ei);
    k_scan1<<<NB_SCAN, SCAN_B>>>();
    k_scan2<<<1, 256>>>();
    k_scan3<<<NB_SCAN, SCAN_B>>>();
    k_scatter<<<(E_EDGES + TPB - 1) / TPB, TPB>>>(ei);
    // layers
    k_sage1_csr<<<(N_NODES + 7) / 8, TPB>>>(x);
    k_sage1_gemm<<<(N_NODES * H_F + TPB - 1) / TPB, TPB>>>(x, W1l, W1r, b1, g1, be1, m1, v1);
    k_gat_gemm<<<N_NODES / 32, TPB>>>(Wg, att_src, att_dst);
    k_gat_csr<<<(N_NODES + 7) / 8, TPB>>>(bg, g2, be2, m2, v2);
    k_sage3_csr<<<(N_NODES + 7) / 8, TPB>>>();
    k_sage3_gemm<<<(N_NODES * HO_F + TPB - 1) / TPB, TPB>>>(x, W3l, W3r, b3, g3, be3, m3, v3, Wskip, bskip);
    k_classifier<<<(N_NODES * 32 + TPB - 1) / TPB, TPB>>>(Wc1, bc1, Wc2, bc2, out);
}